// round 16
// baseline (speedup 1.0000x reference)
#include <cuda_runtime.h>
#include <cuda_fp16.h>
#include <cstdint>

#define NPTS    16384
#define BATCH   16
#define HID     512
#define EMB     64
#define TSTEPS  8
#define OUTC    218
#define NSTEP   8            // K = 512 in 64-wide k-chunks
#define NCHUNK5 16

// ---- scratch (static device allocations) ----
__device__ __align__(128) __half g_A[NPTS * 512];    // ah per row (16 MB)
__device__ __align__(128) __half g_Wc[HID * 512];    // wh, [n][k] K contig
__device__ float g_vt[HID * TSTEPS];          // heatmap vt [j][t]
__device__ float g_part[4 * NPTS * 32];       // [bn][p][t*4+c] head partials (8 MB)
__device__ float g_pp[BATCH * NCHUNK5 * HID];
__device__ float g_base4[4][BATCH][HID];      // act layer-1 partials (k-split 4)
__device__ float g_tv[TSTEPS][HID];           // act traj part + b1
__device__ __align__(16) float g_w2T[OUTC * HID];  // act_w2 transposed [o][k]

// ============================ PTX helpers ====================================
__device__ __forceinline__ uint32_t smem_u32(const void* p) {
    uint32_t a;
    asm("{ .reg .u64 t; cvta.to.shared.u64 t, %1; cvt.u32.u64 %0, t; }" : "=r"(a) : "l"(p));
    return a;
}
#define CP_ASYNC16(dst, src) \
    asm volatile("cp.async.cg.shared.global [%0], [%1], 16;" :: "r"(dst), "l"(src) : "memory")
#define CP_COMMIT() asm volatile("cp.async.commit_group;" ::: "memory")
#define CP_WAIT(n)  asm volatile("cp.async.wait_group %0;" :: "n"(n) : "memory")

#define LDSM4(d, a) \
    asm volatile("ldmatrix.sync.aligned.m8n8.x4.shared.b16 {%0,%1,%2,%3}, [%4];" \
                 : "=r"((d)[0]), "=r"((d)[1]), "=r"((d)[2]), "=r"((d)[3]) : "r"(a))

#define MMA_F16(c, a, b) \
    asm volatile( \
        "mma.sync.aligned.m16n8k16.row.col.f32.f16.f16.f32 " \
        "{%0,%1,%2,%3},{%4,%5,%6,%7},{%8,%9},{%0,%1,%2,%3};" \
        : "+f"((c)[0]), "+f"((c)[1]), "+f"((c)[2]), "+f"((c)[3]) \
        : "r"((a)[0]), "r"((a)[1]), "r"((a)[2]), "r"((a)[3]), "r"((b)[0]), "r"((b)[1]))

// ============================================================================
// KPRE: merged preprocessing, grid-partitioned (unchanged).
// ============================================================================
__global__ __launch_bounds__(256) void kpre(const float* __restrict__ pe,
                                            const float* __restrict__ w1,
                                            const float* __restrict__ b1,
                                            const float* __restrict__ traj,
                                            const int* __restrict__ np,
                                            const float* __restrict__ aw2) {
    __shared__ float s[32][33];
    const int bid = blockIdx.x, tid = threadIdx.x;

    if (bid < 4096) {
        int idx = bid * 256 + tid;
        int row = idx >> 6, g = idx & 63;
        const float* src = pe + (size_t)row * HID + g * 8;
        float4 f0 = *(const float4*)src;
        float4 f1 = *(const float4*)(src + 4);
        float f[8] = {f0.x, f0.y, f0.z, f0.w, f1.x, f1.y, f1.z, f1.w};
        __align__(16) __half hi[8];
#pragma unroll
        for (int i = 0; i < 8; i++) hi[i] = __float2half_rn(f[i]);
        *(uint4*)(g_A + (size_t)row * 512 + g * 8) = *(const uint4*)hi;
    } else if (bid < 4368) {
        const int id = bid - 4096;
        const int x = id & 15, y = id >> 4;       // y: 0..16
        const int tx = tid & 31, ty = tid >> 5;
        if (y == 16) {
            const int j = x * 32 + tx;
            const int t = ty;
            float acc = b1[j];
#pragma unroll 8
            for (int e = 0; e < EMB; e++)
                acc += traj[t * EMB + e] * w1[(size_t)(HID + e) * HID + j];
            g_vt[j * TSTEPS + t] = acc;
            return;
        }
        const int kb = y * 32, nb = x * 32;
#pragma unroll
        for (int i = 0; i < 4; i++) {
            int k = ty + i * 8;
            s[k][tx] = w1[(size_t)(kb + k) * HID + nb + tx];
        }
        __syncthreads();
#pragma unroll
        for (int i = 0; i < 4; i++) {
            int nr = ty + i * 8;
            g_Wc[(size_t)(nb + nr) * 512 + kb + tx] = __float2half_rn(s[tx][nr]);
        }
    } else if (bid < 4880) {
        const int id = bid - 4368;
        const int b = id & 15, colh = (id >> 4) & 1, chunk = id >> 5;
        const int col = colh * 256 + tid;
        int start = 0;
        for (int i = 0; i < b; i++) start += np[i];
        const int len = np[b];
        const int c0 = start + (chunk * len) / NCHUNK5;
        const int c1 = start + ((chunk + 1) * len) / NCHUNK5;
        float m0 = -1e30f, m1 = -1e30f, m2 = -1e30f, m3 = -1e30f;
        int p = c0;
        for (; p + 3 < c1; p += 4) {
            m0 = fmaxf(m0, pe[(size_t)p * HID + col]);
            m1 = fmaxf(m1, pe[(size_t)(p + 1) * HID + col]);
            m2 = fmaxf(m2, pe[(size_t)(p + 2) * HID + col]);
            m3 = fmaxf(m3, pe[(size_t)(p + 3) * HID + col]);
        }
        for (; p < c1; p++) m0 = fmaxf(m0, pe[(size_t)p * HID + col]);
        g_pp[(b * NCHUNK5 + chunk) * HID + col] = fmaxf(fmaxf(m0, m1), fmaxf(m2, m3));
    } else {
        const int id = bid - 4880;
        const int ox = id % 7, ky = id / 7;       // 7 x 16 tiles
        const int o0 = ox * 32, k0 = ky * 32;
        const int tx = tid & 31, ty = tid >> 5;
#pragma unroll
        for (int i = 0; i < 4; i++) {
            int k = k0 + ty + i * 8;
            int o = o0 + tx;
            s[ty + i * 8][tx] = (o < OUTC) ? aw2[(size_t)k * OUTC + o] : 0.f;
        }
        __syncthreads();
#pragma unroll
        for (int i = 0; i < 4; i++) {
            int o = o0 + ty + i * 8;
            if (o < OUTC) g_w2T[(size_t)o * HID + k0 + tx] = s[tx][ty + i * 8];
        }
    }
}

// ============================================================================
// KGEMM: 64-wide k-chunks, 3-stage (A 32KB + B 16KB = 48KB/stage -> 144KB).
//   bid <  256: GEMM tile (CTA 256m x 128n, 512 thr, 16 warps 4m x 4n),
//               fused head epilogue -> g_part
//   bid >= 256: aux — [256,320): base4 partials; [320,328): tv
// ============================================================================
#define STG_B   49152
#define SMEM_KG (3 * STG_B)

__global__ __launch_bounds__(512) void kgemm(const float* __restrict__ w2,
                                             const float* __restrict__ aw1,
                                             const float* __restrict__ ab1,
                                             const float* __restrict__ traj) {
    extern __shared__ char smem[];
    const int bid = blockIdx.x;
    const int tid = threadIdx.x;

    if (bid >= 256) {
        const int id = bid - 256;
        if (id < 64) {
            float* pc = (float*)smem;
            const int b = id >> 2, kq = id & 3;
            if (tid < 128) {
                const int k = kq * 128 + tid;
                float m = -1e30f;
#pragma unroll
                for (int c = 0; c < NCHUNK5; c++)
                    m = fmaxf(m, g_pp[(b * NCHUNK5 + c) * HID + k]);
                pc[tid] = m;
            }
            __syncthreads();
            const int j = tid;
            float acc = 0.f;
            const float* wbase = aw1 + (size_t)(kq * 128) * HID + j;
#pragma unroll 4
            for (int k = 0; k < 128; k++) acc += pc[k] * wbase[(size_t)k * HID];
            g_base4[kq][b][j] = acc;
        } else {
            const int t = id - 64, j = tid;
            float acc = ab1[j];
#pragma unroll 8
            for (int e = 0; e < EMB; e++)
                acc += traj[t * EMB + e] * aw1[(size_t)(HID + e) * HID + j];
            g_tv[t][j] = acc;
        }
        return;
    }

    const uint32_t sb = smem_u32(smem);
    const int lane = tid & 31, w = tid >> 5;
    const int wm = w >> 2, wn = w & 3;          // warp grid 4(m) x 4(n)
    const int bm = bid & 63, bn = bid >> 6;
    const int ti = lane >> 3, r = lane & 7;

    float acc[4][4][4];
#pragma unroll
    for (int i = 0; i < 4; i++)
#pragma unroll
        for (int j = 0; j < 4; j++)
#pragma unroll
            for (int q = 0; q < 4; q++) acc[i][j][q] = 0.f;

    const char* Ab = (const char*)g_A + (size_t)bm * 256 * 1024;
    const char* Bb = (const char*)g_Wc + (size_t)bn * 128 * 1024;

    // 64-wide chunk: A 256x64 (2048 16B tiles' worth: 8 chunks/row),
    // B 128x64.  Tile-major: ((m8*8 + k8)*8 + r)*16.
    auto stage_load = [&](int s) {
        const int buf = s % 3;
        const int kof = s * 64;
        const uint32_t dA = sb + buf * STG_B;
        const uint32_t dB = dA + 32768;
#pragma unroll
        for (int h = 0; h < 4; h++) {
            int q = h * 512 + tid;
            int m = q >> 3, kg = q & 7;
            uint32_t off = (uint32_t)((((m >> 3) * 8 + kg) * 8 + (m & 7)) * 16);
            CP_ASYNC16(dA + off, Ab + (size_t)m * 1024 + (size_t)(kof + kg * 8) * 2);
        }
#pragma unroll
        for (int h = 0; h < 2; h++) {
            int q = h * 512 + tid;
            int n = q >> 3, kg = q & 7;
            uint32_t off = (uint32_t)((((n >> 3) * 8 + kg) * 8 + (n & 7)) * 16);
            CP_ASYNC16(dB + off, Bb + (size_t)n * 1024 + (size_t)(kof + kg * 8) * 2);
        }
        CP_COMMIT();
    };

    stage_load(0); stage_load(1);

    for (int s = 0; s < NSTEP; s++) {
        CP_WAIT(1);
        __syncthreads();
        if (s + 2 < NSTEP) stage_load(s + 2); else CP_COMMIT();
        const uint32_t sA = sb + (s % 3) * STG_B;
        const uint32_t sB = sA + 32768;
#pragma unroll
        for (int kk = 0; kk < 4; kk++) {
            uint32_t af[4][4];
#pragma unroll
            for (int i = 0; i < 4; i++) {
                int m8 = (wm * 4 + i) * 2 + (ti & 1);
                int k8 = kk * 2 + (ti >> 1);
                LDSM4(af[i], sA + (uint32_t)(((m8 * 8 + k8) * 8 + r) * 16));
            }
            uint32_t bf[2][4];
#pragma unroll
            for (int pj = 0; pj < 2; pj++) {
                int n8 = wn * 4 + pj * 2 + (ti >> 1);
                int k8 = kk * 2 + (ti & 1);
                LDSM4(bf[pj], sB + (uint32_t)(((n8 * 8 + k8) * 8 + r) * 16));
            }
#pragma unroll
            for (int i = 0; i < 4; i++)
#pragma unroll
                for (int j = 0; j < 4; j++)
                    MMA_F16(acc[i][j], af[i], &bf[j >> 1][(j & 1) * 2]);
        }
    }
    CP_WAIT(0);
    __syncthreads();

    // ---- fused head partial epilogue (unchanged; this CTA's 128 cols) ----
    float* vts  = (float*)smem;            // [128][8]  4KB
    float* w2s  = (float*)(smem + 4096);   // [128][4]  2KB
    float* rbuf = (float*)(smem + 8192);   // [32 rows][4 wn][32] 16KB
    for (int idx = tid; idx < 128 * TSTEPS; idx += 512) vts[idx] = g_vt[bn * 1024 + idx];
    if (tid < 128 * 4) w2s[tid] = w2[bn * 512 + tid];
    __syncthreads();

#pragma unroll
    for (int i = 0; i < 4; i++) {
#pragma unroll
        for (int half = 0; half < 2; half++) {
            float part[32];
#pragma unroll
            for (int v = 0; v < 32; v++) part[v] = 0.f;
#pragma unroll
            for (int j = 0; j < 4; j++) {
#pragma unroll
                for (int col = 0; col < 2; col++) {
                    const float u = acc[i][j][half * 2 + col];
                    const int nl = wn * 32 + j * 8 + (lane & 3) * 2 + col;
                    const float* vt8 = vts + nl * 8;
                    float4 wv = *(const float4*)(w2s + nl * 4);
#pragma unroll
                    for (int t = 0; t < 8; t++) {
                        float x = u + vt8[t];
                        float h = fmaxf(x, 0.02f * x);
                        part[t * 4 + 0] += h * wv.x;
                        part[t * 4 + 1] += h * wv.y;
                        part[t * 4 + 2] += h * wv.z;
                        part[t * 4 + 3] += h * wv.w;
                    }
                }
            }
#pragma unroll
            for (int o = 1; o <= 2; o <<= 1)
#pragma unroll
                for (int v = 0; v < 32; v++)
                    part[v] += __shfl_xor_sync(0xffffffffu, part[v], o);
            if ((lane & 3) == 0) {
                int row = wm * 8 + (lane >> 2);       // 0..31
                float* d = rbuf + (row * 4 + wn) * 32;
#pragma unroll
                for (int v = 0; v < 32; v++) d[v] = part[v];
            }
            __syncthreads();
#pragma unroll
            for (int sl = 0; sl < 2; sl++) {
                const int slot = sl * 512 + tid;      // 1024 slots
                const int row = slot >> 5, v = slot & 31;
                const float* src = rbuf + row * 128 + v;
                float sum = src[0] + src[32] + src[64] + src[96];
                const int m_g = bm * 256 + (row >> 3) * 64 + i * 16 + half * 8 + (row & 7);
                g_part[((size_t)bn * NPTS + m_g) * 32 + v] = sum;
            }
            __syncthreads();
        }
    }
}

// ============================================================================
// KFINAL: [0,128) per-(b,t) softmax + coord sum; [128,256) act layer 2.
// ============================================================================
__global__ __launch_bounds__(512) void kfinal(const int* __restrict__ np,
                                              const float* __restrict__ coords,
                                              const float* __restrict__ b2,
                                              const float* __restrict__ ab2,
                                              float* __restrict__ out) {
    const int bid = blockIdx.x, tid = threadIdx.x;

    if (bid >= 128) {
        __shared__ float hid[TSTEPS][516];
        const int id = bid - 128;
        const int b = id >> 3, oc = id & 7;

        {
            float base = g_base4[0][b][tid] + g_base4[1][b][tid] +
                         g_base4[2][b][tid] + g_base4[3][b][tid];
#pragma unroll
            for (int t = 0; t < 8; t++) {
                float v = base + g_tv[t][tid];
                hid[t][tid] = v >= 0.f ? v : 0.02f * v;
            }
        }
        __syncthreads();

        const int o_l = tid >> 4, t = (tid >> 1) & 7, h = tid & 1;
        const int o = oc * 28 + o_l;
        const bool valid = (o_l < 28) && (o < OUTC);
        float a = 0.f;
        if (valid) {
            const float* wrow = g_w2T + (size_t)o * HID + h * 256;
            const float* hrow = hid[t] + h * 256;
#pragma unroll 8
            for (int k = 0; k < 256; k += 4) {
                float4 wv = *(const float4*)(wrow + k);
                a += hrow[k] * wv.x + hrow[k + 1] * wv.y +
                     hrow[k + 2] * wv.z + hrow[k + 3] * wv.w;
            }
        }
        a += __shfl_xor_sync(0xffffffffu, a, 1);
        if (valid && h == 0) {
            float tot = a + ab2[o];
            const int bt = b * 8 + t;
            const int XT = BATCH * TSTEPS * 3;
            const int XR = BATCH * TSTEPS * 216;
            if (o < 216)       out[XT + bt * 216 + o] = tot;
            else if (o == 216) out[XT + XR + bt] = tot;
            else               out[XT + XR + BATCH * TSTEPS + bt] = tot;
        }
        return;
    }

    const int b = bid >> 3, t = bid & 7;
    const int lane = tid & 31, warp = tid >> 5;
    int start = 0;
    for (int i = 0; i < b; i++) start += np[i];
    const int end = start + np[b];

    __shared__ float sred[16][4];
    __shared__ float mshared;

    float m = -1e30f;
    for (int p = start + tid; p < end; p += 512) {
        float l = g_part[(size_t)p * 32 + t * 4]
                + g_part[((size_t)NPTS + p) * 32 + t * 4]
                + g_part[((size_t)2 * NPTS + p) * 32 + t * 4]
                + g_part[((size_t)3 * NPTS + p) * 32 + t * 4];
        m = fmaxf(m, l);
    }
#pragma unroll
    for (int o = 16; o > 0; o >>= 1) m = fmaxf(m, __shfl_down_sync(0xffffffffu, m, o));
    if (lane == 0) sred[warp][0] = m;
    __syncthreads();
    if (tid == 0) {
        float v = sred[0][0];
        for (int i = 1; i < 16; i++) v = fmaxf(v, sred[i][0]);
        mshared = v;
    }
    __syncthreads();
    const float mx = mshared;
    const float b2x = b2[1], b2y = b2[2], b2z = b2[3];

    float s = 0.f, sx = 0.f, sy = 0.f, sz = 0.f;
    for (int p = start + tid; p < end; p += 512) {
        float4 v0 = *(const float4*)(g_part + (size_t)p * 32 + t * 4);
        float4 v1 = *(const float4*)(g_part + ((size_t)NPTS + p) * 32 + t * 4);
        float4 v2 = *(const float4*)(g_part + ((size_t)2 * NPTS + p) * 32 + t * 4);
        float4 v3 = *(const float4*)(g_part + ((size_t)3 * NPTS + p) * 32 + t * 4);
        float l  = v0.x + v1.x + v2.x + v3.x;
        float dx = v0.y + v1.y + v2.y + v3.y;
        float dy = v0.z + v1.z + v2.z + v3.z;
        float dz = v0.w + v1.w + v2.w + v3.w;
        float e = expf(l - mx);
        s  += e;
        sx += e * (coords[p * 3 + 0] + dx + b2x);
        sy += e * (coords[p * 3 + 1] + dy + b2y);
        sz += e * (coords[p * 3 + 2] + dz + b2z);
    }
#pragma unroll
    for (int o = 16; o > 0; o >>= 1) {
        s  += __shfl_down_sync(0xffffffffu, s,  o);
        sx += __shfl_down_sync(0xffffffffu, sx, o);
        sy += __shfl_down_sync(0xffffffffu, sy, o);
        sz += __shfl_down_sync(0xffffffffu, sz, o);
    }
    if (lane == 0) { sred[warp][0] = s; sred[warp][1] = sx; sred[warp][2] = sy; sred[warp][3] = sz; }
    __syncthreads();
    if (tid == 0) {
        float ts = 0, tx = 0, ty = 0, tz = 0;
        for (int i = 0; i < 16; i++) { ts += sred[i][0]; tx += sred[i][1]; ty += sred[i][2]; tz += sred[i][3]; }
        float inv = 1.f / ts;
        out[(b * 8 + t) * 3 + 0] = tx * inv;
        out[(b * 8 + t) * 3 + 1] = ty * inv;
        out[(b * 8 + t) * 3 + 2] = tz * inv;
    }
}

// ============================================================================
extern "C" void kernel_launch(void* const* d_in, const int* in_sizes, int n_in,
                              void* d_out, int out_size) {
    const float* pe     = (const float*)d_in[0];
    const float* coords = (const float*)d_in[1];
    const float* traj   = (const float*)d_in[2];
    const float* hw1    = (const float*)d_in[3];
    const float* hb1    = (const float*)d_in[4];
    const float* hw2    = (const float*)d_in[5];
    const float* hb2    = (const float*)d_in[6];
    const float* aw1    = (const float*)d_in[7];
    const float* ab1    = (const float*)d_in[8];
    const float* aw2    = (const float*)d_in[9];
    const float* ab2    = (const float*)d_in[10];
    const int*   np     = (const int*)d_in[11];
    float* out = (float*)d_out;

    static bool attr_set = false;
    if (!attr_set) {
        cudaFuncSetAttribute(kgemm, cudaFuncAttributeMaxDynamicSharedMemorySize, SMEM_KG);
        attr_set = true;
    }

    kpre<<<4992, 256>>>(pe, hw1, hb1, traj, np, aw2);                // 1
    kgemm<<<328, 512, SMEM_KG>>>(hw2, aw1, ab1, traj);               // 2
    kfinal<<<256, 512>>>(np, coords, hb2, ab2, out);                 // 3
}

// round 17
// speedup vs baseline: 1.1357x; 1.1357x over previous
#include <cuda_runtime.h>
#include <cuda_fp16.h>
#include <cstdint>

#define NPTS    16384
#define BATCH   16
#define HID     512
#define EMB     64
#define TSTEPS  8
#define OUTC    218
#define NSTEP   16           // K = 512 in 32-wide k-steps
#define NCHUNK5 16

// ---- scratch (static device allocations) ----
__device__ __align__(128) __half g_A[NPTS * 512];    // ah per row (16 MB)
__device__ __align__(128) __half g_Wc[HID * 512];    // wh, [n][k] K contig
__device__ float g_vt[HID * TSTEPS];          // heatmap vt [j][t]
__device__ float g_part[4 * NPTS * 32];       // [bn][p][t*4+c] head partials (8 MB)
__device__ float g_pp[BATCH * NCHUNK5 * HID];
__device__ float g_base4[4][BATCH][HID];      // act layer-1 partials (k-split 4)
__device__ float g_tv[TSTEPS][HID];           // act traj part + b1
__device__ __align__(16) float g_w2T[OUTC * HID];  // act_w2 transposed [o][k]

// ============================ PTX helpers ====================================
__device__ __forceinline__ uint32_t smem_u32(const void* p) {
    uint32_t a;
    asm("{ .reg .u64 t; cvta.to.shared.u64 t, %1; cvt.u32.u64 %0, t; }" : "=r"(a) : "l"(p));
    return a;
}
#define CP_ASYNC16(dst, src) \
    asm volatile("cp.async.cg.shared.global [%0], [%1], 16;" :: "r"(dst), "l"(src) : "memory")
#define CP_COMMIT() asm volatile("cp.async.commit_group;" ::: "memory")
#define CP_WAIT(n)  asm volatile("cp.async.wait_group %0;" :: "n"(n) : "memory")

#define LDSM4(d, a) \
    asm volatile("ldmatrix.sync.aligned.m8n8.x4.shared.b16 {%0,%1,%2,%3}, [%4];" \
                 : "=r"((d)[0]), "=r"((d)[1]), "=r"((d)[2]), "=r"((d)[3]) : "r"(a))

#define MMA_F16(c, a, b) \
    asm volatile( \
        "mma.sync.aligned.m16n8k16.row.col.f32.f16.f16.f32 " \
        "{%0,%1,%2,%3},{%4,%5,%6,%7},{%8,%9},{%0,%1,%2,%3};" \
        : "+f"((c)[0]), "+f"((c)[1]), "+f"((c)[2]), "+f"((c)[3]) \
        : "r"((a)[0]), "r"((a)[1]), "r"((a)[2]), "r"((a)[3]), "r"((b)[0]), "r"((b)[1]))

// ============================================================================
// KPRE: merged preprocessing, grid-partitioned (unchanged).
// ============================================================================
__global__ __launch_bounds__(256) void kpre(const float* __restrict__ pe,
                                            const float* __restrict__ w1,
                                            const float* __restrict__ b1,
                                            const float* __restrict__ traj,
                                            const int* __restrict__ np,
                                            const float* __restrict__ aw2) {
    __shared__ float s[32][33];
    const int bid = blockIdx.x, tid = threadIdx.x;

    if (bid < 4096) {
        int idx = bid * 256 + tid;
        int row = idx >> 6, g = idx & 63;
        const float* src = pe + (size_t)row * HID + g * 8;
        float4 f0 = *(const float4*)src;
        float4 f1 = *(const float4*)(src + 4);
        float f[8] = {f0.x, f0.y, f0.z, f0.w, f1.x, f1.y, f1.z, f1.w};
        __align__(16) __half hi[8];
#pragma unroll
        for (int i = 0; i < 8; i++) hi[i] = __float2half_rn(f[i]);
        *(uint4*)(g_A + (size_t)row * 512 + g * 8) = *(const uint4*)hi;
    } else if (bid < 4368) {
        const int id = bid - 4096;
        const int x = id & 15, y = id >> 4;       // y: 0..16
        const int tx = tid & 31, ty = tid >> 5;
        if (y == 16) {
            const int j = x * 32 + tx;
            const int t = ty;
            float acc = b1[j];
#pragma unroll 8
            for (int e = 0; e < EMB; e++)
                acc += traj[t * EMB + e] * w1[(size_t)(HID + e) * HID + j];
            g_vt[j * TSTEPS + t] = acc;
            return;
        }
        const int kb = y * 32, nb = x * 32;
#pragma unroll
        for (int i = 0; i < 4; i++) {
            int k = ty + i * 8;
            s[k][tx] = w1[(size_t)(kb + k) * HID + nb + tx];
        }
        __syncthreads();
#pragma unroll
        for (int i = 0; i < 4; i++) {
            int nr = ty + i * 8;
            g_Wc[(size_t)(nb + nr) * 512 + kb + tx] = __float2half_rn(s[tx][nr]);
        }
    } else if (bid < 4880) {
        const int id = bid - 4368;
        const int b = id & 15, colh = (id >> 4) & 1, chunk = id >> 5;
        const int col = colh * 256 + tid;
        int start = 0;
        for (int i = 0; i < b; i++) start += np[i];
        const int len = np[b];
        const int c0 = start + (chunk * len) / NCHUNK5;
        const int c1 = start + ((chunk + 1) * len) / NCHUNK5;
        float m0 = -1e30f, m1 = -1e30f, m2 = -1e30f, m3 = -1e30f;
        int p = c0;
        for (; p + 3 < c1; p += 4) {
            m0 = fmaxf(m0, pe[(size_t)p * HID + col]);
            m1 = fmaxf(m1, pe[(size_t)(p + 1) * HID + col]);
            m2 = fmaxf(m2, pe[(size_t)(p + 2) * HID + col]);
            m3 = fmaxf(m3, pe[(size_t)(p + 3) * HID + col]);
        }
        for (; p < c1; p++) m0 = fmaxf(m0, pe[(size_t)p * HID + col]);
        g_pp[(b * NCHUNK5 + chunk) * HID + col] = fmaxf(fmaxf(m0, m1), fmaxf(m2, m3));
    } else {
        const int id = bid - 4880;
        const int ox = id % 7, ky = id / 7;       // 7 x 16 tiles
        const int o0 = ox * 32, k0 = ky * 32;
        const int tx = tid & 31, ty = tid >> 5;
#pragma unroll
        for (int i = 0; i < 4; i++) {
            int k = k0 + ty + i * 8;
            int o = o0 + tx;
            s[ty + i * 8][tx] = (o < OUTC) ? aw2[(size_t)k * OUTC + o] : 0.f;
        }
        __syncthreads();
#pragma unroll
        for (int i = 0; i < 4; i++) {
            int o = o0 + ty + i * 8;
            if (o < OUTC) g_w2T[(size_t)o * HID + k0 + tx] = s[tx][ty + i * 8];
        }
    }
}

// ============================================================================
// KGEMM (persistent 2-tile): 128 GEMM CTAs (0.86 waves), each does two
//   256m x 128n tiles (bm = (bid&31) + half*32, bn = bid>>5), R15-verified
//   6-stage K=32 mainloop + fused head epilogue per tile.
//   bid >= 128: aux — [128,192): base4 partials; [192,200): tv
// ============================================================================
#define STG_B   24576
#define SMEM_KG (6 * STG_B)

__global__ __launch_bounds__(512) void kgemm(const float* __restrict__ w2,
                                             const float* __restrict__ aw1,
                                             const float* __restrict__ ab1,
                                             const float* __restrict__ traj) {
    extern __shared__ char smem[];
    const int bid = blockIdx.x;
    const int tid = threadIdx.x;

    if (bid >= 128) {
        const int id = bid - 128;
        if (id < 64) {
            float* pc = (float*)smem;
            const int b = id >> 2, kq = id & 3;
            if (tid < 128) {
                const int k = kq * 128 + tid;
                float m = -1e30f;
#pragma unroll
                for (int c = 0; c < NCHUNK5; c++)
                    m = fmaxf(m, g_pp[(b * NCHUNK5 + c) * HID + k]);
                pc[tid] = m;
            }
            __syncthreads();
            const int j = tid;
            float acc = 0.f;
            const float* wbase = aw1 + (size_t)(kq * 128) * HID + j;
#pragma unroll 4
            for (int k = 0; k < 128; k++) acc += pc[k] * wbase[(size_t)k * HID];
            g_base4[kq][b][j] = acc;
        } else {
            const int t = id - 64, j = tid;
            float acc = ab1[j];
#pragma unroll 8
            for (int e = 0; e < EMB; e++)
                acc += traj[t * EMB + e] * aw1[(size_t)(HID + e) * HID + j];
            g_tv[t][j] = acc;
        }
        return;
    }

    const uint32_t sb = smem_u32(smem);
    const int lane = tid & 31, w = tid >> 5;
    const int wm = w >> 2, wn = w & 3;          // warp grid 4(m) x 4(n)
    const int bn = bid >> 5;
    const int ti = lane >> 3, r = lane & 7;

    for (int half_t = 0; half_t < 2; half_t++) {
        const int bm = (bid & 31) + half_t * 32;

        float acc[4][4][4];
#pragma unroll
        for (int i = 0; i < 4; i++)
#pragma unroll
            for (int j = 0; j < 4; j++)
#pragma unroll
                for (int q = 0; q < 4; q++) acc[i][j][q] = 0.f;

        const char* Ab = (const char*)g_A + (size_t)bm * 256 * 1024;
        const char* Bb = (const char*)g_Wc + (size_t)bn * 128 * 1024;

        auto stage_load = [&](int s) {
            const int buf = s % 6;
            const int kof = s * 32;
            const uint32_t dA = sb + buf * STG_B;
            const uint32_t dB = dA + 16384;
#pragma unroll
            for (int h = 0; h < 2; h++) {
                int q = h * 512 + tid;
                int m = q >> 2, kg = q & 3;
                uint32_t off = (uint32_t)((((m >> 3) * 4 + kg) * 8 + (m & 7)) * 16);
                CP_ASYNC16(dA + off, Ab + (size_t)m * 1024 + (size_t)(kof + kg * 8) * 2);
            }
            {
                int n = tid >> 2, kg = tid & 3;
                uint32_t off = (uint32_t)((((n >> 3) * 4 + kg) * 8 + (n & 7)) * 16);
                CP_ASYNC16(dB + off, Bb + (size_t)n * 1024 + (size_t)(kof + kg * 8) * 2);
            }
            CP_COMMIT();
        };

        stage_load(0); stage_load(1); stage_load(2); stage_load(3); stage_load(4);

        for (int s = 0; s < NSTEP; s++) {
            CP_WAIT(4);
            __syncthreads();
            const uint32_t sA = sb + (s % 6) * STG_B;
            const uint32_t sB = sA + 16384;
#pragma unroll
            for (int kk = 0; kk < 2; kk++) {
                uint32_t af[4][4];
#pragma unroll
                for (int i = 0; i < 4; i++) {
                    int m8 = (wm * 4 + i) * 2 + (ti & 1);
                    int k8 = kk * 2 + (ti >> 1);
                    LDSM4(af[i], sA + (uint32_t)(((m8 * 4 + k8) * 8 + r) * 16));
                }
                uint32_t bf[2][4];
#pragma unroll
                for (int pj = 0; pj < 2; pj++) {
                    int n8 = wn * 4 + pj * 2 + (ti >> 1);
                    int k8 = kk * 2 + (ti & 1);
                    LDSM4(bf[pj], sB + (uint32_t)(((n8 * 4 + k8) * 8 + r) * 16));
                }
#pragma unroll
                for (int i = 0; i < 4; i++)
#pragma unroll
                    for (int j = 0; j < 4; j++)
                        MMA_F16(acc[i][j], af[i], &bf[j >> 1][(j & 1) * 2]);
            }
            if (s + 5 < NSTEP) stage_load(s + 5); else CP_COMMIT();
        }
        CP_WAIT(0);
        __syncthreads();

        // ---- fused head partial epilogue (this CTA's 128 cols) ----
        float* vts  = (float*)smem;            // [128][8]  4KB
        float* w2s  = (float*)(smem + 4096);   // [128][4]  2KB
        float* rbuf = (float*)(smem + 8192);   // [32 rows][4 wn][32] 16KB
        for (int idx = tid; idx < 128 * TSTEPS; idx += 512) vts[idx] = g_vt[bn * 1024 + idx];
        if (tid < 128 * 4) w2s[tid] = w2[bn * 512 + tid];
        __syncthreads();

#pragma unroll
        for (int i = 0; i < 4; i++) {
#pragma unroll
            for (int half = 0; half < 2; half++) {
                float part[32];
#pragma unroll
                for (int v = 0; v < 32; v++) part[v] = 0.f;
#pragma unroll
                for (int j = 0; j < 4; j++) {
#pragma unroll
                    for (int col = 0; col < 2; col++) {
                        const float u = acc[i][j][half * 2 + col];
                        const int nl = wn * 32 + j * 8 + (lane & 3) * 2 + col;
                        const float* vt8 = vts + nl * 8;
                        float4 wv = *(const float4*)(w2s + nl * 4);
#pragma unroll
                        for (int t = 0; t < 8; t++) {
                            float x = u + vt8[t];
                            float h = fmaxf(x, 0.02f * x);
                            part[t * 4 + 0] += h * wv.x;
                            part[t * 4 + 1] += h * wv.y;
                            part[t * 4 + 2] += h * wv.z;
                            part[t * 4 + 3] += h * wv.w;
                        }
                    }
                }
#pragma unroll
                for (int o = 1; o <= 2; o <<= 1)
#pragma unroll
                    for (int v = 0; v < 32; v++)
                        part[v] += __shfl_xor_sync(0xffffffffu, part[v], o);
                if ((lane & 3) == 0) {
                    int row = wm * 8 + (lane >> 2);       // 0..31
                    float* d = rbuf + (row * 4 + wn) * 32;
#pragma unroll
                    for (int v = 0; v < 32; v++) d[v] = part[v];
                }
                __syncthreads();
#pragma unroll
                for (int sl = 0; sl < 2; sl++) {
                    const int slot = sl * 512 + tid;      // 1024 slots
                    const int row = slot >> 5, v = slot & 31;
                    const float* src = rbuf + row * 128 + v;
                    float sum = src[0] + src[32] + src[64] + src[96];
                    const int m_g = bm * 256 + (row >> 3) * 64 + i * 16 + half * 8 + (row & 7);
                    g_part[((size_t)bn * NPTS + m_g) * 32 + v] = sum;
                }
                __syncthreads();
            }
        }
    }
}

// ============================================================================
// KFINAL: [0,128) per-(b,t) softmax + coord sum; [128,256) act layer 2.
// ============================================================================
__global__ __launch_bounds__(512) void kfinal(const int* __restrict__ np,
                                              const float* __restrict__ coords,
                                              const float* __restrict__ b2,
                                              const float* __restrict__ ab2,
                                              float* __restrict__ out) {
    const int bid = blockIdx.x, tid = threadIdx.x;

    if (bid >= 128) {
        __shared__ float hid[TSTEPS][516];
        const int id = bid - 128;
        const int b = id >> 3, oc = id & 7;

        {
            float base = g_base4[0][b][tid] + g_base4[1][b][tid] +
                         g_base4[2][b][tid] + g_base4[3][b][tid];
#pragma unroll
            for (int t = 0; t < 8; t++) {
                float v = base + g_tv[t][tid];
                hid[t][tid] = v >= 0.f ? v : 0.02f * v;
            }
        }
        __syncthreads();

        const int o_l = tid >> 4, t = (tid >> 1) & 7, h = tid & 1;
        const int o = oc * 28 + o_l;
        const bool valid = (o_l < 28) && (o < OUTC);
        float a = 0.f;
        if (valid) {
            const float* wrow = g_w2T + (size_t)o * HID + h * 256;
            const float* hrow = hid[t] + h * 256;
#pragma unroll 8
            for (int k = 0; k < 256; k += 4) {
                float4 wv = *(const float4*)(wrow + k);
                a += hrow[k] * wv.x + hrow[k + 1] * wv.y +
                     hrow[k + 2] * wv.z + hrow[k + 3] * wv.w;
            }
        }
        a += __shfl_xor_sync(0xffffffffu, a, 1);
        if (valid && h == 0) {
            float tot = a + ab2[o];
            const int bt = b * 8 + t;
            const int XT = BATCH * TSTEPS * 3;
            const int XR = BATCH * TSTEPS * 216;
            if (o < 216)       out[XT + bt * 216 + o] = tot;
            else if (o == 216) out[XT + XR + bt] = tot;
            else               out[XT + XR + BATCH * TSTEPS + bt] = tot;
        }
        return;
    }

    const int b = bid >> 3, t = bid & 7;
    const int lane = tid & 31, warp = tid >> 5;
    int start = 0;
    for (int i = 0; i < b; i++) start += np[i];
    const int end = start + np[b];

    __shared__ float sred[16][4];
    __shared__ float mshared;

    float m = -1e30f;
    for (int p = start + tid; p < end; p += 512) {
        float l = g_part[(size_t)p * 32 + t * 4]
                + g_part[((size_t)NPTS + p) * 32 + t * 4]
                + g_part[((size_t)2 * NPTS + p) * 32 + t * 4]
                + g_part[((size_t)3 * NPTS + p) * 32 + t * 4];
        m = fmaxf(m, l);
    }
#pragma unroll
    for (int o = 16; o > 0; o >>= 1) m = fmaxf(m, __shfl_down_sync(0xffffffffu, m, o));
    if (lane == 0) sred[warp][0] = m;
    __syncthreads();
    if (tid == 0) {
        float v = sred[0][0];
        for (int i = 1; i < 16; i++) v = fmaxf(v, sred[i][0]);
        mshared = v;
    }
    __syncthreads();
    const float mx = mshared;
    const float b2x = b2[1], b2y = b2[2], b2z = b2[3];

    float s = 0.f, sx = 0.f, sy = 0.f, sz = 0.f;
    for (int p = start + tid; p < end; p += 512) {
        float4 v0 = *(const float4*)(g_part + (size_t)p * 32 + t * 4);
        float4 v1 = *(const float4*)(g_part + ((size_t)NPTS + p) * 32 + t * 4);
        float4 v2 = *(const float4*)(g_part + ((size_t)2 * NPTS + p) * 32 + t * 4);
        float4 v3 = *(const float4*)(g_part + ((size_t)3 * NPTS + p) * 32 + t * 4);
        float l  = v0.x + v1.x + v2.x + v3.x;
        float dx = v0.y + v1.y + v2.y + v3.y;
        float dy = v0.z + v1.z + v2.z + v3.z;
        float dz = v0.w + v1.w + v2.w + v3.w;
        float e = expf(l - mx);
        s  += e;
        sx += e * (coords[p * 3 + 0] + dx + b2x);
        sy += e * (coords[p * 3 + 1] + dy + b2y);
        sz += e * (coords[p * 3 + 2] + dz + b2z);
    }
#pragma unroll
    for (int o = 16; o > 0; o >>= 1) {
        s  += __shfl_down_sync(0xffffffffu, s,  o);
        sx += __shfl_down_sync(0xffffffffu, sx, o);
        sy += __shfl_down_sync(0xffffffffu, sy, o);
        sz += __shfl_down_sync(0xffffffffu, sz, o);
    }
    if (lane == 0) { sred[warp][0] = s; sred[warp][1] = sx; sred[warp][2] = sy; sred[warp][3] = sz; }
    __syncthreads();
    if (tid == 0) {
        float ts = 0, tx = 0, ty = 0, tz = 0;
        for (int i = 0; i < 16; i++) { ts += sred[i][0]; tx += sred[i][1]; ty += sred[i][2]; tz += sred[i][3]; }
        float inv = 1.f / ts;
        out[(b * 8 + t) * 3 + 0] = tx * inv;
        out[(b * 8 + t) * 3 + 1] = ty * inv;
        out[(b * 8 + t) * 3 + 2] = tz * inv;
    }
}

// ============================================================================
extern "C" void kernel_launch(void* const* d_in, const int* in_sizes, int n_in,
                              void* d_out, int out_size) {
    const float* pe     = (const float*)d_in[0];
    const float* coords = (const float*)d_in[1];
    const float* traj   = (const float*)d_in[2];
    const float* hw1    = (const float*)d_in[3];
    const float* hb1    = (const float*)d_in[4];
    const float* hw2    = (const float*)d_in[5];
    const float* hb2    = (const float*)d_in[6];
    const float* aw1    = (const float*)d_in[7];
    const float* ab1    = (const float*)d_in[8];
    const float* aw2    = (const float*)d_in[9];
    const float* ab2    = (const float*)d_in[10];
    const int*   np     = (const int*)d_in[11];
    float* out = (float*)d_out;

    static bool attr_set = false;
    if (!attr_set) {
        cudaFuncSetAttribute(kgemm, cudaFuncAttributeMaxDynamicSharedMemorySize, SMEM_KG);
        attr_set = true;
    }

    kpre<<<4992, 256>>>(pe, hw1, hb1, traj, np, aw2);                // 1
    kgemm<<<200, 512, SMEM_KG>>>(hw2, aw1, ab1, traj);               // 2
    kfinal<<<256, 512>>>(np, coords, hb2, ab2, out);                 // 3
}